// round 3
// baseline (speedup 1.0000x reference)
#include <cuda_runtime.h>
#include <cstdint>

#define NB 2
#define NN 30000
#define NE 120000
#define KF 512
#define NH 4
#define DH 128
#define OF 512
#define NBH 8
#define LN_EPS 1e-5f

__device__ float        g_t[(size_t)NBH * NN * DH];  // [b*4+h][n][d]
__device__ float        g_w2[KF * OF];               // [k][h*128+d]
__device__ float        g_ssrc[NBH * NN];
__device__ float        g_sdst[NBH * NN];
__device__ float        g_sc[(size_t)NBH * NE];
__device__ unsigned int g_maxb[NBH];
__device__ float        g_sum[NBH];
__device__ int          g_cnt[NN];
__device__ int          g_off[NN + 1];
__device__ int          g_cur[NN];
__device__ int          g_eid[NE];
__device__ int          g_is64;

__device__ __forceinline__ unsigned f2ord(float f) {
    unsigned u = __float_as_uint(f);
    return (u & 0x80000000u) ? ~u : (u | 0x80000000u);
}
__device__ __forceinline__ float ord2f(unsigned u) {
    return (u & 0x80000000u) ? __uint_as_float(u ^ 0x80000000u) : __uint_as_float(~u);
}
__device__ __forceinline__ int esrc(const void* ep, int e, int is64) {
    return is64 ? (int)((const long long*)ep)[e] : ((const int*)ep)[e];
}
__device__ __forceinline__ int edst(const void* ep, int e, int is64) {
    return is64 ? (int)((const long long*)ep)[NE + e] : ((const int*)ep)[NE + e];
}

__global__ void k_detect(const int* ei32) {
    if (threadIdx.x == 0) {
        int ok = 1;
        for (int j = 0; j < 64; j++)
            if (ei32[2 * j + 1] != 0) ok = 0;
        g_is64 = ok;
    }
}

__global__ void k_init() {
    int i = blockIdx.x * blockDim.x + threadIdx.x;
    if (i < NN) g_cnt[i] = 0;
    if (i < NBH) { g_maxb[i] = f2ord(-1e30f); g_sum[i] = 0.f; }
}

__global__ void k_wt(const float* __restrict__ W) {
    int i = blockIdx.x * blockDim.x + threadIdx.x;  // over H*K*D
    if (i >= NH * KF * DH) return;
    int h = i / (KF * DH), r = i % (KF * DH), k = r / DH, d = r % DH;
    g_w2[k * OF + h * DH + d] = W[i];
}

#define BM 64
#define BN 64
#define BK 32
__global__ __launch_bounds__(256) void k_gemm(const float* __restrict__ x) {
    __shared__ float Xs[BK][BM + 4];
    __shared__ float Ws[BK][BN];
    int tid = threadIdx.x;
    int bm = blockIdx.x * BM, bn = blockIdx.y * BN, b = blockIdx.z;
    int tx = tid & 15, ty = tid >> 4;
    float acc[4][4] = {};
    const float* xb = x + (size_t)b * NN * KF;

    for (int kt = 0; kt < KF; kt += BK) {
        #pragma unroll
        for (int it = 0; it < 2; it++) {
            int row = (tid >> 3) + it * 32;
            int k4 = (tid & 7) * 4;
            int gr = bm + row;
            float4 v = make_float4(0.f, 0.f, 0.f, 0.f);
            if (gr < NN) v = *(const float4*)(xb + (size_t)gr * KF + kt + k4);
            Xs[k4][row] = v.x; Xs[k4 + 1][row] = v.y;
            Xs[k4 + 2][row] = v.z; Xs[k4 + 3][row] = v.w;
        }
        #pragma unroll
        for (int it = 0; it < 2; it++) {
            int kr = (tid >> 4) + it * 16;
            int j4 = (tid & 15) * 4;
            *(float4*)&Ws[kr][j4] = *(const float4*)(g_w2 + (size_t)(kt + kr) * OF + bn + j4);
        }
        __syncthreads();
        #pragma unroll
        for (int kk = 0; kk < BK; kk++) {
            float xr[4], wr[4];
            *(float4*)xr = *(float4*)&Xs[kk][ty * 4];
            *(float4*)wr = *(float4*)&Ws[kk][tx * 4];
            #pragma unroll
            for (int i = 0; i < 4; i++)
                #pragma unroll
                for (int j = 0; j < 4; j++) acc[i][j] += xr[i] * wr[j];
        }
        __syncthreads();
    }
    #pragma unroll
    for (int i = 0; i < 4; i++) {
        int n = bm + ty * 4 + i;
        if (n >= NN) break;
        #pragma unroll
        for (int j = 0; j < 4; j++) {
            int col = bn + tx * 4 + j;
            int h = col >> 7, d = col & 127;
            g_t[((size_t)(b * NH + h) * NN + n) * DH + d] = acc[i][j];
        }
    }
}

__global__ void k_scores(const float* __restrict__ a) {
    int wid = threadIdx.x >> 5, lid = threadIdx.x & 31;
    int r = blockIdx.x * 8 + wid;               // r = bh*NN + n
    if (r >= NBH * NN) return;
    int bh = r / NN;
    int h = bh & 3;
    float4 v = *(const float4*)(g_t + (size_t)r * DH + lid * 4);
    const float* as = a + h * 2 * DH + lid * 4;
    const float* ad = as + DH;
    float d1 = v.x * as[0] + v.y * as[1] + v.z * as[2] + v.w * as[3];
    float d2 = v.x * ad[0] + v.y * ad[1] + v.z * ad[2] + v.w * ad[3];
    #pragma unroll
    for (int o = 16; o > 0; o >>= 1) {
        d1 += __shfl_down_sync(0xffffffffu, d1, o);
        d2 += __shfl_down_sync(0xffffffffu, d2, o);
    }
    if (lid == 0) { g_ssrc[r] = d1; g_sdst[r] = d2; }
}

__global__ void k_edge(const void* ep) {
    __shared__ float red[256];
    int is64 = g_is64;
    int bh = blockIdx.y;
    int e = blockIdx.x * 256 + threadIdx.x;
    float s = -1e30f;
    if (e < NE) {
        int sn = esrc(ep, e, is64), dn = edst(ep, e, is64);
        s = g_ssrc[bh * NN + sn] + g_sdst[bh * NN + dn];
        s = (s > 0.f) ? s : 0.2f * s;
        g_sc[(size_t)bh * NE + e] = s;
    }
    red[threadIdx.x] = s;
    __syncthreads();
    for (int o = 128; o > 0; o >>= 1) {
        if (threadIdx.x < o) red[threadIdx.x] = fmaxf(red[threadIdx.x], red[threadIdx.x + o]);
        __syncthreads();
    }
    if (threadIdx.x == 0) atomicMax(&g_maxb[bh], f2ord(red[0]));
}

__global__ void k_exps() {
    __shared__ float red[256];
    int bh = blockIdx.y;
    int e = blockIdx.x * 256 + threadIdx.x;
    float mx = ord2f(g_maxb[bh]);
    float p = 0.f;
    if (e < NE) {
        p = __expf(g_sc[(size_t)bh * NE + e] - mx);
        g_sc[(size_t)bh * NE + e] = p;
    }
    red[threadIdx.x] = p;
    __syncthreads();
    for (int o = 128; o > 0; o >>= 1) {
        if (threadIdx.x < o) red[threadIdx.x] += red[threadIdx.x + o];
        __syncthreads();
    }
    if (threadIdx.x == 0) atomicAdd(&g_sum[bh], red[0]);
}

__global__ void k_count(const void* ep) {
    int e = blockIdx.x * 256 + threadIdx.x;
    if (e < NE) atomicAdd(&g_cnt[edst(ep, e, g_is64)], 1);
}

__global__ __launch_bounds__(1024) void k_scan() {
    __shared__ int s[1024];
    int tid = threadIdx.x;
    const int C = (NN + 1023) / 1024;
    int base = tid * C;
    int sum = 0;
    for (int i = 0; i < C; i++) { int idx = base + i; if (idx < NN) sum += g_cnt[idx]; }
    s[tid] = sum;
    __syncthreads();
    for (int o = 1; o < 1024; o <<= 1) {
        int v = (tid >= o) ? s[tid - o] : 0;
        __syncthreads();
        s[tid] += v;
        __syncthreads();
    }
    int run = s[tid] - sum;
    for (int i = 0; i < C; i++) {
        int idx = base + i;
        if (idx < NN) { g_off[idx] = run; g_cur[idx] = run; run += g_cnt[idx]; }
    }
    if (tid == 1023) g_off[NN] = run;
}

__global__ void k_fill(const void* ep) {
    int e = blockIdx.x * 256 + threadIdx.x;
    if (e < NE) {
        int pos = atomicAdd(&g_cur[edst(ep, e, g_is64)], 1);
        g_eid[pos] = e;
    }
}

__global__ __launch_bounds__(128) void k_agg(const void* ep,
                                             const float* __restrict__ gamma,
                                             const float* __restrict__ beta,
                                             float* __restrict__ out) {
    __shared__ float red[8];
    int is64 = g_is64;
    int n = blockIdx.x, b = blockIdx.y;
    int tid = threadIdx.x;
    float inv[NH];
    #pragma unroll
    for (int h = 0; h < NH; h++) inv[h] = 1.f / g_sum[b * NH + h];
    float acc[NH] = {0.f, 0.f, 0.f, 0.f};
    int e0 = g_off[n], e1 = g_off[n + 1];
    for (int idx = e0; idx < e1; idx++) {
        int e = g_eid[idx];
        int sn = esrc(ep, e, is64);
        #pragma unroll
        for (int h = 0; h < NH; h++) {
            int bh = b * NH + h;
            float w = g_sc[(size_t)bh * NE + e] * inv[h];
            acc[h] += w * g_t[((size_t)bh * NN + sn) * DH + tid];
        }
    }
    // LayerNorm over the 512 values (4 heads x 128 lanes)
    float s1 = acc[0] + acc[1] + acc[2] + acc[3];
    float s2 = acc[0] * acc[0] + acc[1] * acc[1] + acc[2] * acc[2] + acc[3] * acc[3];
    #pragma unroll
    for (int o = 16; o > 0; o >>= 1) {
        s1 += __shfl_down_sync(0xffffffffu, s1, o);
        s2 += __shfl_down_sync(0xffffffffu, s2, o);
    }
    if ((tid & 31) == 0) { red[(tid >> 5) * 2] = s1; red[(tid >> 5) * 2 + 1] = s2; }
    __syncthreads();
    float t1 = red[0] + red[2] + red[4] + red[6];
    float t2 = red[1] + red[3] + red[5] + red[7];
    float mu = t1 / (float)OF;
    float var = t2 / (float)OF - mu * mu;
    float rs = rsqrtf(var + LN_EPS);
    float* op = out + ((size_t)b * NN + n) * OF;
    #pragma unroll
    for (int h = 0; h < NH; h++) {
        int j = h * DH + tid;
        op[j] = (acc[h] - mu) * rs * gamma[j] + beta[j];
    }
}

extern "C" void kernel_launch(void* const* d_in, const int* in_sizes, int n_in,
                              void* d_out, int out_size) {
    const float* x     = (const float*)d_in[0];
    const void*  ei    = d_in[1];
    const float* W     = (const float*)d_in[2];
    const float* a     = (const float*)d_in[3];
    const float* gamma = (const float*)d_in[4];
    const float* beta  = (const float*)d_in[5];
    float* out = (float*)d_out;

    k_detect<<<1, 32>>>((const int*)ei);
    k_init<<<(NN + 255) / 256, 256>>>();
    k_wt<<<(NH * KF * DH + 255) / 256, 256>>>(W);
    {
        dim3 g((NN + BM - 1) / BM, OF / BN, NB);
        k_gemm<<<g, 256>>>(x);
    }
    k_scores<<<(NBH * NN + 7) / 8, 256>>>(a);
    {
        dim3 g((NE + 255) / 256, NBH);
        k_edge<<<g, 256>>>(ei);
        k_exps<<<g, 256>>>();
    }
    k_count<<<(NE + 255) / 256, 256>>>(ei);
    k_scan<<<1, 1024>>>();
    k_fill<<<(NE + 255) / 256, 256>>>(ei);
    {
        dim3 g(NN, NB);
        k_agg<<<g, 128>>>(ei, gamma, beta, out);
    }
}

// round 5
// speedup vs baseline: 1.8029x; 1.8029x over previous
#include <cuda_runtime.h>
#include <cuda_bf16.h>
#include <cstdint>

#define NB 2
#define NN 30000
#define NE 120000
#define KF 512
#define NH 4
#define DH 128
#define OF 512
#define NBH 8
#define LN_EPS 1e-5f

__device__ float         g_t[(size_t)NBH * NN * DH];  // [b*4+h][n][d]
__device__ __nv_bfloat16 g_xhi[(size_t)NB * NN * KF];
__device__ __nv_bfloat16 g_xlo[(size_t)NB * NN * KF];
__device__ __nv_bfloat16 g_wthi[OF * KF];  // [n][k], n = h*128+d
__device__ __nv_bfloat16 g_wtlo[OF * KF];
__device__ float         g_ssrc[NBH * NN];
__device__ float         g_sdst[NBH * NN];
__device__ float         g_sc[(size_t)NBH * NE];
__device__ unsigned int  g_maxb[NBH];
__device__ float         g_sum[NBH];
__device__ int           g_cnt[NN];
__device__ int           g_off[NN + 1];
__device__ int           g_cur[NN];
__device__ int           g_eid[NE];
__device__ int           g_is64;

__device__ __forceinline__ unsigned f2ord(float f) {
    unsigned u = __float_as_uint(f);
    return (u & 0x80000000u) ? ~u : (u | 0x80000000u);
}
__device__ __forceinline__ float ord2f(unsigned u) {
    return (u & 0x80000000u) ? __uint_as_float(u ^ 0x80000000u) : __uint_as_float(~u);
}
__device__ __forceinline__ int esrc(const void* ep, int e, int is64) {
    return is64 ? (int)((const long long*)ep)[e] : ((const int*)ep)[e];
}
__device__ __forceinline__ int edst(const void* ep, int e, int is64) {
    return is64 ? (int)((const long long*)ep)[NE + e] : ((const int*)ep)[NE + e];
}
__device__ __forceinline__ uint32_t smem_u32(const void* p) {
    uint32_t a;
    asm("{ .reg .u64 t; cvta.to.shared.u64 t, %1; cvt.u32.u64 %0, t; }" : "=r"(a) : "l"(p));
    return a;
}
__device__ __forceinline__ void cpa16(uint32_t dst, const void* src, int sz) {
    asm volatile("cp.async.ca.shared.global [%0], [%1], 16, %2;"
                 :: "r"(dst), "l"(src), "r"(sz) : "memory");
}

// ---------------- prep kernels ----------------
__global__ void k_detect(const int* ei32) {
    if (threadIdx.x == 0) {
        int ok = 1;
        for (int j = 0; j < 64; j++)
            if (ei32[2 * j + 1] != 0) ok = 0;
        g_is64 = ok;
    }
}
__global__ void k_init() {
    int i = blockIdx.x * blockDim.x + threadIdx.x;
    if (i < NN) g_cnt[i] = 0;
    if (i < NBH) { g_maxb[i] = f2ord(-1e30f); g_sum[i] = 0.f; }
}
__global__ void k_splitx(const float* __restrict__ x) {
    size_t i = (size_t)blockIdx.x * blockDim.x + threadIdx.x;
    if (i >= (size_t)NB * NN * KF / 4) return;
    float4 v = ((const float4*)x)[i];
    __nv_bfloat16 h0 = __float2bfloat16(v.x), h1 = __float2bfloat16(v.y);
    __nv_bfloat16 h2 = __float2bfloat16(v.z), h3 = __float2bfloat16(v.w);
    __nv_bfloat16 l0 = __float2bfloat16(v.x - __bfloat162float(h0));
    __nv_bfloat16 l1 = __float2bfloat16(v.y - __bfloat162float(h1));
    __nv_bfloat16 l2 = __float2bfloat16(v.z - __bfloat162float(h2));
    __nv_bfloat16 l3 = __float2bfloat16(v.w - __bfloat162float(h3));
    ((ushort4*)g_xhi)[i] = make_ushort4(__bfloat16_as_ushort(h0), __bfloat16_as_ushort(h1),
                                        __bfloat16_as_ushort(h2), __bfloat16_as_ushort(h3));
    ((ushort4*)g_xlo)[i] = make_ushort4(__bfloat16_as_ushort(l0), __bfloat16_as_ushort(l1),
                                        __bfloat16_as_ushort(l2), __bfloat16_as_ushort(l3));
}
__global__ void k_convw(const float* __restrict__ W) {
    int i = blockIdx.x * blockDim.x + threadIdx.x;  // h,k,d
    if (i >= NH * KF * DH) return;
    int h = i / (KF * DH), r = i % (KF * DH), k = r / DH, d = r % DH;
    float v = W[i];
    __nv_bfloat16 hi = __float2bfloat16(v);
    __nv_bfloat16 lo = __float2bfloat16(v - __bfloat162float(hi));
    int n = h * DH + d;
    g_wthi[(size_t)n * KF + k] = hi;
    g_wtlo[(size_t)n * KF + k] = lo;
}

// ---------------- mma.sync GEMM: 128x128 per CTA, K=512, 3-term bf16 -------
// SMEM: 2 buffers x [A(hi,lo) 128x32 + B(hi,lo) 128x32], row pitch 40 bf16.
#define PITCHB 80            // bytes per row (40 bf16)
#define TERMB  10240         // one 128-row tile
#define MATB   20480         // hi+lo
#define BUFB   40960         // A + B
#define SMEMB  81920

__device__ __forceinline__ void load_chunk(uint32_t sb, int buf, int kc,
                                           int m0, int bn, size_t xb, int tid) {
    #pragma unroll
    for (int i = 0; i < 8; i++) {
        int idx = i * 256 + tid;
        int mat = idx >> 10;
        int r = idx & 1023;
        int term = r >> 9;
        int rr = r & 511;
        int row = rr >> 2, seg = rr & 3;
        uint32_t dst = sb + buf * BUFB + mat * MATB + term * TERMB + row * PITCHB + seg * 16;
        const __nv_bfloat16* src;
        int sz = 16;
        if (mat == 0) {
            int gr = m0 + row;
            src = (term ? g_xlo : g_xhi) + xb + (size_t)gr * KF + kc * 32 + seg * 8;
            if (gr >= NN) sz = 0;
        } else {
            src = (term ? g_wtlo : g_wthi) + (size_t)(bn + row) * KF + kc * 32 + seg * 8;
        }
        cpa16(dst, src, sz);
    }
    asm volatile("cp.async.commit_group;" ::: "memory");
}

__global__ __launch_bounds__(256) void k_gemm_mma() {
    extern __shared__ float4 smf4[];
    char* sm = (char*)smf4;
    uint32_t sb = smem_u32(sm);
    int tid = threadIdx.x, lid = tid & 31, wid = tid >> 5;
    int gid = lid >> 2, tig = lid & 3;
    int wM = wid & 3, wN = wid >> 2;
    int m0 = blockIdx.x * 128, bn = blockIdx.y * 128, b = blockIdx.z;
    size_t xb = (size_t)b * NN * KF;

    float acc[2][8][4];
    #pragma unroll
    for (int mi = 0; mi < 2; mi++)
        #pragma unroll
        for (int ni = 0; ni < 8; ni++)
            #pragma unroll
            for (int q = 0; q < 4; q++) acc[mi][ni][q] = 0.f;

    load_chunk(sb, 0, 0, m0, bn, xb, tid);

    for (int kc = 0; kc < 16; kc++) {
        if (kc < 15) {
            load_chunk(sb, (kc + 1) & 1, kc + 1, m0, bn, xb, tid);
            asm volatile("cp.async.wait_group 1;" ::: "memory");
        } else {
            asm volatile("cp.async.wait_group 0;" ::: "memory");
        }
        __syncthreads();
        const char* As = sm + (kc & 1) * BUFB;
        const char* Bs = As + MATB;
        #pragma unroll
        for (int t = 0; t < 3; t++) {
            const char* Ab = As + ((t == 1) ? TERMB : 0);
            const char* Bb = Bs + ((t == 2) ? TERMB : 0);
            #pragma unroll
            for (int s = 0; s < 2; s++) {
                int k0 = s * 16 + tig * 2;
                uint32_t af[2][4];
                #pragma unroll
                for (int mi = 0; mi < 2; mi++) {
                    const char* p = Ab + (wM * 32 + mi * 16 + gid) * PITCHB + k0 * 2;
                    af[mi][0] = *(const uint32_t*)p;
                    af[mi][1] = *(const uint32_t*)(p + 8 * PITCHB);
                    af[mi][2] = *(const uint32_t*)(p + 16);
                    af[mi][3] = *(const uint32_t*)(p + 8 * PITCHB + 16);
                }
                #pragma unroll
                for (int ni = 0; ni < 8; ni++) {
                    const char* p = Bb + (wN * 64 + ni * 8 + gid) * PITCHB + k0 * 2;
                    uint32_t b0 = *(const uint32_t*)p;
                    uint32_t b1 = *(const uint32_t*)(p + 16);
                    #pragma unroll
                    for (int mi = 0; mi < 2; mi++) {
                        float* c = acc[mi][ni];
                        asm volatile(
                            "mma.sync.aligned.m16n8k16.row.col.f32.bf16.bf16.f32 "
                            "{%0,%1,%2,%3}, {%4,%5,%6,%7}, {%8,%9}, {%0,%1,%2,%3};"
                            : "+f"(c[0]), "+f"(c[1]), "+f"(c[2]), "+f"(c[3])
                            : "r"(af[mi][0]), "r"(af[mi][1]), "r"(af[mi][2]), "r"(af[mi][3]),
                              "r"(b0), "r"(b1));
                    }
                }
            }
        }
        __syncthreads();
    }

    // epilogue: write g_t[b][h][n][d], h = blockIdx.y
    float* base = g_t + (size_t)(b * NH + blockIdx.y) * NN * DH;
    #pragma unroll
    for (int mi = 0; mi < 2; mi++) {
        #pragma unroll
        for (int ni = 0; ni < 8; ni++) {
            int row = m0 + wM * 32 + mi * 16 + gid;
            int d0 = wN * 64 + ni * 8 + tig * 2;
            if (row < NN)
                *(float2*)(base + (size_t)row * DH + d0) =
                    make_float2(acc[mi][ni][0], acc[mi][ni][1]);
            if (row + 8 < NN)
                *(float2*)(base + (size_t)(row + 8) * DH + d0) =
                    make_float2(acc[mi][ni][2], acc[mi][ni][3]);
        }
    }
}

// ---------------- rest of the pipeline ----------------
__global__ void k_scores(const float* __restrict__ a) {
    int wid = threadIdx.x >> 5, lid = threadIdx.x & 31;
    int r = blockIdx.x * 8 + wid;
    if (r >= NBH * NN) return;
    int bh = r / NN;
    int h = bh & 3;
    float4 v = *(const float4*)(g_t + (size_t)r * DH + lid * 4);
    const float* as = a + h * 2 * DH + lid * 4;
    const float* ad = as + DH;
    float d1 = v.x * as[0] + v.y * as[1] + v.z * as[2] + v.w * as[3];
    float d2 = v.x * ad[0] + v.y * ad[1] + v.z * ad[2] + v.w * ad[3];
    #pragma unroll
    for (int o = 16; o > 0; o >>= 1) {
        d1 += __shfl_down_sync(0xffffffffu, d1, o);
        d2 += __shfl_down_sync(0xffffffffu, d2, o);
    }
    if (lid == 0) { g_ssrc[r] = d1; g_sdst[r] = d2; }
}
__global__ void k_edge(const void* ep) {
    __shared__ float red[256];
    int is64 = g_is64;
    int bh = blockIdx.y;
    int e = blockIdx.x * 256 + threadIdx.x;
    float s = -1e30f;
    if (e < NE) {
        int sn = esrc(ep, e, is64), dn = edst(ep, e, is64);
        s = g_ssrc[bh * NN + sn] + g_sdst[bh * NN + dn];
        s = (s > 0.f) ? s : 0.2f * s;
        g_sc[(size_t)bh * NE + e] = s;
    }
    red[threadIdx.x] = s;
    __syncthreads();
    for (int o = 128; o > 0; o >>= 1) {
        if (threadIdx.x < o) red[threadIdx.x] = fmaxf(red[threadIdx.x], red[threadIdx.x + o]);
        __syncthreads();
    }
    if (threadIdx.x == 0) atomicMax(&g_maxb[bh], f2ord(red[0]));
}
__global__ void k_exps() {
    __shared__ float red[256];
    int bh = blockIdx.y;
    int e = blockIdx.x * 256 + threadIdx.x;
    float mx = ord2f(g_maxb[bh]);
    float p = 0.f;
    if (e < NE) {
        p = __expf(g_sc[(size_t)bh * NE + e] - mx);
        g_sc[(size_t)bh * NE + e] = p;
    }
    red[threadIdx.x] = p;
    __syncthreads();
    for (int o = 128; o > 0; o >>= 1) {
        if (threadIdx.x < o) red[threadIdx.x] += red[threadIdx.x + o];
        __syncthreads();
    }
    if (threadIdx.x == 0) atomicAdd(&g_sum[bh], red[0]);
}
__global__ void k_count(const void* ep) {
    int e = blockIdx.x * 256 + threadIdx.x;
    if (e < NE) atomicAdd(&g_cnt[edst(ep, e, g_is64)], 1);
}
__global__ __launch_bounds__(1024) void k_scan() {
    __shared__ int s[1024];
    int tid = threadIdx.x;
    const int C = (NN + 1023) / 1024;
    int base = tid * C;
    int sum = 0;
    for (int i = 0; i < C; i++) { int idx = base + i; if (idx < NN) sum += g_cnt[idx]; }
    s[tid] = sum;
    __syncthreads();
    for (int o = 1; o < 1024; o <<= 1) {
        int v = (tid >= o) ? s[tid - o] : 0;
        __syncthreads();
        s[tid] += v;
        __syncthreads();
    }
    int run = s[tid] - sum;
    for (int i = 0; i < C; i++) {
        int idx = base + i;
        if (idx < NN) { g_off[idx] = run; g_cur[idx] = run; run += g_cnt[idx]; }
    }
    if (tid == 1023) g_off[NN] = run;
}
__global__ void k_fill(const void* ep) {
    int e = blockIdx.x * 256 + threadIdx.x;
    if (e < NE) {
        int pos = atomicAdd(&g_cur[edst(ep, e, g_is64)], 1);
        g_eid[pos] = e;
    }
}
__global__ __launch_bounds__(128) void k_agg(const void* ep,
                                             const float* __restrict__ gamma,
                                             const float* __restrict__ beta,
                                             float* __restrict__ out) {
    __shared__ float red[8];
    int is64 = g_is64;
    int n = blockIdx.x, b = blockIdx.y;
    int tid = threadIdx.x;
    float inv[NH];
    #pragma unroll
    for (int h = 0; h < NH; h++) inv[h] = 1.f / g_sum[b * NH + h];
    float acc[NH] = {0.f, 0.f, 0.f, 0.f};
    int e0 = g_off[n], e1 = g_off[n + 1];
    for (int idx = e0; idx < e1; idx++) {
        int e = g_eid[idx];
        int sn = esrc(ep, e, is64);
        #pragma unroll
        for (int h = 0; h < NH; h++) {
            int bh = b * NH + h;
            float w = g_sc[(size_t)bh * NE + e] * inv[h];
            acc[h] += w * g_t[((size_t)bh * NN + sn) * DH + tid];
        }
    }
    float s1 = acc[0] + acc[1] + acc[2] + acc[3];
    float s2 = acc[0] * acc[0] + acc[1] * acc[1] + acc[2] * acc[2] + acc[3] * acc[3];
    #pragma unroll
    for (int o = 16; o > 0; o >>= 1) {
        s1 += __shfl_down_sync(0xffffffffu, s1, o);
        s2 += __shfl_down_sync(0xffffffffu, s2, o);
    }
    if ((tid & 31) == 0) { red[(tid >> 5) * 2] = s1; red[(tid >> 5) * 2 + 1] = s2; }
    __syncthreads();
    float t1 = red[0] + red[2] + red[4] + red[6];
    float t2 = red[1] + red[3] + red[5] + red[7];
    float mu = t1 / (float)OF;
    float var = t2 / (float)OF - mu * mu;
    float rs = rsqrtf(var + LN_EPS);
    float* op = out + ((size_t)b * NN + n) * OF;
    #pragma unroll
    for (int h = 0; h < NH; h++) {
        int j = h * DH + tid;
        op[j] = (acc[h] - mu) * rs * gamma[j] + beta[j];
    }
}

extern "C" void kernel_launch(void* const* d_in, const int* in_sizes, int n_in,
                              void* d_out, int out_size) {
    const float* x     = (const float*)d_in[0];
    const void*  ei    = d_in[1];
    const float* W     = (const float*)d_in[2];
    const float* a     = (const float*)d_in[3];
    const float* gamma = (const float*)d_in[4];
    const float* beta  = (const float*)d_in[5];
    float* out = (float*)d_out;

    cudaFuncSetAttribute(k_gemm_mma, cudaFuncAttributeMaxDynamicSharedMemorySize, SMEMB);

    k_detect<<<1, 32>>>((const int*)ei);
    k_init<<<(NN + 255) / 256, 256>>>();
    k_splitx<<<(NB * NN * KF / 4 + 255) / 256, 256>>>(x);
    k_convw<<<(NH * KF * DH + 255) / 256, 256>>>(W);
    {
        dim3 g((NN + 127) / 128, OF / 128, NB);
        k_gemm_mma<<<g, 256, SMEMB>>>();
    }
    k_scores<<<(NBH * NN + 7) / 8, 256>>>(a);
    {
        dim3 g((NE + 255) / 256, NBH);
        k_edge<<<g, 256>>>(ei);
        k_exps<<<g, 256>>>();
    }
    k_count<<<(NE + 255) / 256, 256>>>(ei);
    k_scan<<<1, 1024>>>();
    k_fill<<<(NE + 255) / 256, 256>>>(ei);
    {
        dim3 g(NN, NB);
        k_agg<<<g, 128>>>(ei, gamma, beta, out);
    }
}

// round 6
// speedup vs baseline: 2.2411x; 1.2431x over previous
#include <cuda_runtime.h>
#include <cuda_bf16.h>
#include <cstdint>

#define NB 2
#define NN 30000
#define NE 120000
#define KF 512
#define NH 4
#define DH 128
#define OF 512
#define NBH 8
#define LN_EPS 1e-5f

__device__ float         g_t[(size_t)NN * NB * OF];   // [n][b][512]
__device__ __nv_bfloat16 g_xhi[(size_t)NB * NN * KF];
__device__ __nv_bfloat16 g_xlo[(size_t)NB * NN * KF];
__device__ __nv_bfloat16 g_wthi[OF * KF];  // [col][k], col = h*128+d
__device__ __nv_bfloat16 g_wtlo[OF * KF];
__device__ float         g_ssrc[(size_t)NN * NBH];    // [n][b*4+h]
__device__ float         g_sdst[(size_t)NN * NBH];
__device__ float         g_sc[(size_t)NE * NBH];      // [e][b*4+h]
__device__ unsigned int  g_maxb[NBH];
__device__ float         g_sum[NBH];
__device__ int           g_cnt[NN];
__device__ int           g_off[NN + 1];
__device__ int           g_cur[NN];
__device__ int           g_eid[NE];
__device__ int           g_is64;

__device__ __forceinline__ unsigned f2ord(float f) {
    unsigned u = __float_as_uint(f);
    return (u & 0x80000000u) ? ~u : (u | 0x80000000u);
}
__device__ __forceinline__ float ord2f(unsigned u) {
    return (u & 0x80000000u) ? __uint_as_float(u ^ 0x80000000u) : __uint_as_float(~u);
}
__device__ __forceinline__ int esrc(const void* ep, int e, int is64) {
    return is64 ? (int)((const long long*)ep)[e] : ((const int*)ep)[e];
}
__device__ __forceinline__ int edst(const void* ep, int e, int is64) {
    return is64 ? (int)((const long long*)ep)[NE + e] : ((const int*)ep)[NE + e];
}
__device__ __forceinline__ uint32_t smem_u32(const void* p) {
    uint32_t a;
    asm("{ .reg .u64 t; cvta.to.shared.u64 t, %1; cvt.u32.u64 %0, t; }" : "=r"(a) : "l"(p));
    return a;
}
__device__ __forceinline__ void cpa16(uint32_t dst, const void* src, int sz) {
    asm volatile("cp.async.ca.shared.global [%0], [%1], 16, %2;"
                 :: "r"(dst), "l"(src), "r"(sz) : "memory");
}

// ---------------- prep kernels ----------------
__global__ void k_detect(const int* ei32) {
    if (threadIdx.x == 0) {
        int ok = 1;
        for (int j = 0; j < 64; j++)
            if (ei32[2 * j + 1] != 0) ok = 0;
        g_is64 = ok;
    }
}
__global__ void k_init() {
    int i = blockIdx.x * blockDim.x + threadIdx.x;
    if (i < NN) g_cnt[i] = 0;
    if (i < NBH) { g_maxb[i] = f2ord(-1e30f); g_sum[i] = 0.f; }
}
__global__ void k_splitx(const float* __restrict__ x) {
    size_t i = (size_t)blockIdx.x * blockDim.x + threadIdx.x;
    if (i >= (size_t)NB * NN * KF / 4) return;
    float4 v = ((const float4*)x)[i];
    __nv_bfloat16 h0 = __float2bfloat16(v.x), h1 = __float2bfloat16(v.y);
    __nv_bfloat16 h2 = __float2bfloat16(v.z), h3 = __float2bfloat16(v.w);
    __nv_bfloat16 l0 = __float2bfloat16(v.x - __bfloat162float(h0));
    __nv_bfloat16 l1 = __float2bfloat16(v.y - __bfloat162float(h1));
    __nv_bfloat16 l2 = __float2bfloat16(v.z - __bfloat162float(h2));
    __nv_bfloat16 l3 = __float2bfloat16(v.w - __bfloat162float(h3));
    ((ushort4*)g_xhi)[i] = make_ushort4(__bfloat16_as_ushort(h0), __bfloat16_as_ushort(h1),
                                        __bfloat16_as_ushort(h2), __bfloat16_as_ushort(h3));
    ((ushort4*)g_xlo)[i] = make_ushort4(__bfloat16_as_ushort(l0), __bfloat16_as_ushort(l1),
                                        __bfloat16_as_ushort(l2), __bfloat16_as_ushort(l3));
}
__global__ void k_convw(const float* __restrict__ W) {
    int i = blockIdx.x * blockDim.x + threadIdx.x;  // h,k,d
    if (i >= NH * KF * DH) return;
    int h = i / (KF * DH), r = i % (KF * DH), k = r / DH, d = r % DH;
    float v = W[i];
    __nv_bfloat16 hi = __float2bfloat16(v);
    __nv_bfloat16 lo = __float2bfloat16(v - __bfloat162float(hi));
    int n = h * DH + d;
    g_wthi[(size_t)n * KF + k] = hi;
    g_wtlo[(size_t)n * KF + k] = lo;
}

// ---------------- mma.sync GEMM: 128x128 per CTA, K=512, 3-term bf16 -------
#define PITCHB 80
#define TERMB  10240
#define MATB   20480
#define BUFB   40960
#define SMEMB  81920

__device__ __forceinline__ void load_chunk(uint32_t sb, int buf, int kc,
                                           int m0, int bn, size_t xb, int tid) {
    #pragma unroll
    for (int i = 0; i < 8; i++) {
        int idx = i * 256 + tid;
        int mat = idx >> 10;
        int r = idx & 1023;
        int term = r >> 9;
        int rr = r & 511;
        int row = rr >> 2, seg = rr & 3;
        uint32_t dst = sb + buf * BUFB + mat * MATB + term * TERMB + row * PITCHB + seg * 16;
        const __nv_bfloat16* src;
        int sz = 16;
        if (mat == 0) {
            int gr = m0 + row;
            src = (term ? g_xlo : g_xhi) + xb + (size_t)gr * KF + kc * 32 + seg * 8;
            if (gr >= NN) sz = 0;
        } else {
            src = (term ? g_wtlo : g_wthi) + (size_t)(bn + row) * KF + kc * 32 + seg * 8;
        }
        cpa16(dst, src, sz);
    }
    asm volatile("cp.async.commit_group;" ::: "memory");
}

#define MMA_BF16(c, a0, a1, a2, a3, b0, b1) \
    asm volatile( \
        "mma.sync.aligned.m16n8k16.row.col.f32.bf16.bf16.f32 " \
        "{%0,%1,%2,%3}, {%4,%5,%6,%7}, {%8,%9}, {%0,%1,%2,%3};" \
        : "+f"((c)[0]), "+f"((c)[1]), "+f"((c)[2]), "+f"((c)[3]) \
        : "r"(a0), "r"(a1), "r"(a2), "r"(a3), "r"(b0), "r"(b1))

__global__ __launch_bounds__(256, 2) void k_gemm_mma(const float* __restrict__ ga) {
    extern __shared__ float4 smf4[];
    char* sm = (char*)smf4;
    uint32_t sb = smem_u32(sm);
    int tid = threadIdx.x, lid = tid & 31, wid = tid >> 5;
    int gid = lid >> 2, tig = lid & 3;
    int wM = wid & 3, wN = wid >> 2;
    int hx = blockIdx.x;                       // head / column block
    int m0 = blockIdx.y * 128, bn = hx * 128;
    int b = blockIdx.z;
    size_t xb = (size_t)b * NN * KF;

    float acc[2][8][4];
    #pragma unroll
    for (int mi = 0; mi < 2; mi++)
        #pragma unroll
        for (int ni = 0; ni < 8; ni++)
            #pragma unroll
            for (int q = 0; q < 4; q++) acc[mi][ni][q] = 0.f;

    load_chunk(sb, 0, 0, m0, bn, xb, tid);

    for (int kc = 0; kc < 16; kc++) {
        if (kc < 15) {
            load_chunk(sb, (kc + 1) & 1, kc + 1, m0, bn, xb, tid);
            asm volatile("cp.async.wait_group 1;" ::: "memory");
        } else {
            asm volatile("cp.async.wait_group 0;" ::: "memory");
        }
        __syncthreads();
        const char* As = sm + (kc & 1) * BUFB;
        const char* Bs = As + MATB;
        #pragma unroll
        for (int s = 0; s < 2; s++) {
            int k0 = s * 16 + tig * 2;
            uint32_t ah[2][4];
            #pragma unroll
            for (int mi = 0; mi < 2; mi++) {
                const char* p = As + (wM * 32 + mi * 16 + gid) * PITCHB + k0 * 2;
                ah[mi][0] = *(const uint32_t*)p;
                ah[mi][1] = *(const uint32_t*)(p + 8 * PITCHB);
                ah[mi][2] = *(const uint32_t*)(p + 16);
                ah[mi][3] = *(const uint32_t*)(p + 8 * PITCHB + 16);
            }
            uint32_t bh_[8][2];
            #pragma unroll
            for (int ni = 0; ni < 8; ni++) {
                const char* p = Bs + (wN * 64 + ni * 8 + gid) * PITCHB + k0 * 2;
                bh_[ni][0] = *(const uint32_t*)p;
                bh_[ni][1] = *(const uint32_t*)(p + 16);
            }
            #pragma unroll
            for (int ni = 0; ni < 8; ni++) {
                MMA_BF16(acc[0][ni], ah[0][0], ah[0][1], ah[0][2], ah[0][3], bh_[ni][0], bh_[ni][1]);
                MMA_BF16(acc[1][ni], ah[1][0], ah[1][1], ah[1][2], ah[1][3], bh_[ni][0], bh_[ni][1]);
            }
            // term: A_lo x B_hi
            #pragma unroll
            for (int mi = 0; mi < 2; mi++) {
                const char* p = As + TERMB + (wM * 32 + mi * 16 + gid) * PITCHB + k0 * 2;
                uint32_t al0 = *(const uint32_t*)p;
                uint32_t al1 = *(const uint32_t*)(p + 8 * PITCHB);
                uint32_t al2 = *(const uint32_t*)(p + 16);
                uint32_t al3 = *(const uint32_t*)(p + 8 * PITCHB + 16);
                #pragma unroll
                for (int ni = 0; ni < 8; ni++)
                    MMA_BF16(acc[mi][ni], al0, al1, al2, al3, bh_[ni][0], bh_[ni][1]);
            }
            // term: A_hi x B_lo
            #pragma unroll
            for (int ni = 0; ni < 8; ni++) {
                const char* p = Bs + TERMB + (wN * 64 + ni * 8 + gid) * PITCHB + k0 * 2;
                uint32_t bl0 = *(const uint32_t*)p;
                uint32_t bl1 = *(const uint32_t*)(p + 16);
                MMA_BF16(acc[0][ni], ah[0][0], ah[0][1], ah[0][2], ah[0][3], bl0, bl1);
                MMA_BF16(acc[1][ni], ah[1][0], ah[1][1], ah[1][2], ah[1][3], bl0, bl1);
            }
        }
        __syncthreads();
    }

    // epilogue: write g_t[n][b][512] + fused s_src/s_dst dots for head hx
    float psrc[2][2] = {{0.f, 0.f}, {0.f, 0.f}};
    float pdst[2][2] = {{0.f, 0.f}, {0.f, 0.f}};
    #pragma unroll
    for (int mi = 0; mi < 2; mi++) {
        #pragma unroll
        for (int ni = 0; ni < 8; ni++) {
            int row = m0 + wM * 32 + mi * 16 + gid;
            int d0 = wN * 64 + ni * 8 + tig * 2;
            float c0 = acc[mi][ni][0], c1 = acc[mi][ni][1];
            float c2 = acc[mi][ni][2], c3 = acc[mi][ni][3];
            float a0 = __ldg(ga + hx * 256 + d0);
            float a1 = __ldg(ga + hx * 256 + d0 + 1);
            float e0 = __ldg(ga + hx * 256 + 128 + d0);
            float e1 = __ldg(ga + hx * 256 + 128 + d0 + 1);
            psrc[mi][0] += c0 * a0 + c1 * a1;
            psrc[mi][1] += c2 * a0 + c3 * a1;
            pdst[mi][0] += c0 * e0 + c1 * e1;
            pdst[mi][1] += c2 * e0 + c3 * e1;
            float* base = g_t + ((size_t)row * NB + b) * OF + hx * 128 + d0;
            if (row < NN) *(float2*)base = make_float2(c0, c1);
            if (row + 8 < NN) *(float2*)(base + 8 * (size_t)(NB * OF)) = make_float2(c2, c3);
        }
    }
    // reduce over tig (lanes 0..3 of each quad)
    #pragma unroll
    for (int mi = 0; mi < 2; mi++)
        #pragma unroll
        for (int hf = 0; hf < 2; hf++) {
            float v = psrc[mi][hf];
            v += __shfl_xor_sync(0xffffffffu, v, 1);
            v += __shfl_xor_sync(0xffffffffu, v, 2);
            psrc[mi][hf] = v;
            float w = pdst[mi][hf];
            w += __shfl_xor_sync(0xffffffffu, w, 1);
            w += __shfl_xor_sync(0xffffffffu, w, 2);
            pdst[mi][hf] = w;
        }
    float* sred = (float*)sm;  // [wN=2][128 rows][2: src/dst]
    if (tig == 0) {
        #pragma unroll
        for (int mi = 0; mi < 2; mi++) {
            int r0 = wM * 32 + mi * 16 + gid;
            sred[(wN * 128 + r0) * 2]     = psrc[mi][0];
            sred[(wN * 128 + r0) * 2 + 1] = pdst[mi][0];
            sred[(wN * 128 + r0 + 8) * 2]     = psrc[mi][1];
            sred[(wN * 128 + r0 + 8) * 2 + 1] = pdst[mi][1];
        }
    }
    __syncthreads();
    if (tid < 128) {
        int n = m0 + tid;
        if (n < NN) {
            float ss = sred[tid * 2] + sred[(128 + tid) * 2];
            float sd = sred[tid * 2 + 1] + sred[(128 + tid) * 2 + 1];
            g_ssrc[(size_t)n * NBH + b * 4 + hx] = ss;
            g_sdst[(size_t)n * NBH + b * 4 + hx] = sd;
        }
    }
}

// ---------------- edge kernels ----------------
__global__ __launch_bounds__(256) void k_edge(const void* ep) {
    __shared__ float wred[8][8];  // [warp][bh]
    int tid = threadIdx.x, wid = tid >> 5, lid = tid & 31;
    int is64 = g_is64;
    int e = blockIdx.x * 256 + tid;
    float sv[8];
    if (e < NE) {
        int sn = esrc(ep, e, is64), dn = edst(ep, e, is64);
        const float* ps = g_ssrc + (size_t)sn * NBH;
        const float* pd = g_sdst + (size_t)dn * NBH;
        #pragma unroll
        for (int i = 0; i < 8; i++) {
            float s = ps[i] + pd[i];
            s = (s > 0.f) ? s : 0.2f * s;
            sv[i] = s;
            g_sc[(size_t)e * NBH + i] = s;
        }
    } else {
        #pragma unroll
        for (int i = 0; i < 8; i++) sv[i] = -1e30f;
    }
    #pragma unroll
    for (int i = 0; i < 8; i++) {
        float m = sv[i];
        #pragma unroll
        for (int o = 16; o > 0; o >>= 1) m = fmaxf(m, __shfl_xor_sync(0xffffffffu, m, o));
        if (lid == 0) wred[wid][i] = m;
    }
    __syncthreads();
    if (tid < 8) {
        float m = wred[0][tid];
        #pragma unroll
        for (int w = 1; w < 8; w++) m = fmaxf(m, wred[w][tid]);
        atomicMax(&g_maxb[tid], f2ord(m));
    }
}
__global__ __launch_bounds__(256) void k_exps() {
    __shared__ float wred[8][8];
    int tid = threadIdx.x, wid = tid >> 5, lid = tid & 31;
    int e = blockIdx.x * 256 + tid;
    float pv[8];
    if (e < NE) {
        #pragma unroll
        for (int i = 0; i < 8; i++) {
            float p = __expf(g_sc[(size_t)e * NBH + i] - ord2f(g_maxb[i]));
            g_sc[(size_t)e * NBH + i] = p;
            pv[i] = p;
        }
    } else {
        #pragma unroll
        for (int i = 0; i < 8; i++) pv[i] = 0.f;
    }
    #pragma unroll
    for (int i = 0; i < 8; i++) {
        float s = pv[i];
        #pragma unroll
        for (int o = 16; o > 0; o >>= 1) s += __shfl_xor_sync(0xffffffffu, s, o);
        if (lid == 0) wred[wid][i] = s;
    }
    __syncthreads();
    if (tid < 8) {
        float s = 0.f;
        #pragma unroll
        for (int w = 0; w < 8; w++) s += wred[w][tid];
        atomicAdd(&g_sum[tid], s);
    }
}

// ---------------- CSR build ----------------
__global__ void k_count(const void* ep) {
    int e = blockIdx.x * 256 + threadIdx.x;
    if (e < NE) atomicAdd(&g_cnt[edst(ep, e, g_is64)], 1);
}
__global__ __launch_bounds__(1024) void k_scan() {
    __shared__ int s[1024];
    int tid = threadIdx.x;
    const int C = (NN + 1023) / 1024;
    int base = tid * C;
    int sum = 0;
    for (int i = 0; i < C; i++) { int idx = base + i; if (idx < NN) sum += g_cnt[idx]; }
    s[tid] = sum;
    __syncthreads();
    for (int o = 1; o < 1024; o <<= 1) {
        int v = (tid >= o) ? s[tid - o] : 0;
        __syncthreads();
        s[tid] += v;
        __syncthreads();
    }
    int run = s[tid] - sum;
    for (int i = 0; i < C; i++) {
        int idx = base + i;
        if (idx < NN) { g_off[idx] = run; g_cur[idx] = run; run += g_cnt[idx]; }
    }
    if (tid == 1023) g_off[NN] = run;
}
__global__ void k_fill(const void* ep) {
    int e = blockIdx.x * 256 + threadIdx.x;
    if (e < NE) {
        int pos = atomicAdd(&g_cur[edst(ep, e, g_is64)], 1);
        g_eid[pos] = e;
    }
}

// ---------------- aggregate + layernorm ----------------
__global__ __launch_bounds__(128) void k_agg(const void* ep,
                                             const float* __restrict__ gamma,
                                             const float* __restrict__ beta,
                                             float* __restrict__ out) {
    __shared__ float red[8];
    int is64 = g_is64;
    int n = blockIdx.x;
    int tid = threadIdx.x;
    float acc[NB][NH] = {};
    int e0 = g_off[n], e1 = g_off[n + 1];
    for (int idx = e0; idx < e1; idx++) {
        int e = g_eid[idx];
        int sn = esrc(ep, e, is64);
        const float* trow = g_t + (size_t)sn * (NB * OF);
        float4 w0 = *(const float4*)(g_sc + (size_t)e * NBH);
        float4 w1 = *(const float4*)(g_sc + (size_t)e * NBH + 4);
        acc[0][0] += w0.x * trow[tid];
        acc[0][1] += w0.y * trow[128 + tid];
        acc[0][2] += w0.z * trow[256 + tid];
        acc[0][3] += w0.w * trow[384 + tid];
        acc[1][0] += w1.x * trow[512 + tid];
        acc[1][1] += w1.y * trow[640 + tid];
        acc[1][2] += w1.z * trow[768 + tid];
        acc[1][3] += w1.w * trow[896 + tid];
    }
    #pragma unroll
    for (int b = 0; b < NB; b++) {
        #pragma unroll
        for (int h = 0; h < NH; h++) acc[b][h] *= (1.f / g_sum[b * 4 + h]);
        float s1 = acc[b][0] + acc[b][1] + acc[b][2] + acc[b][3];
        float s2 = acc[b][0] * acc[b][0] + acc[b][1] * acc[b][1] +
                   acc[b][2] * acc[b][2] + acc[b][3] * acc[b][3];
        #pragma unroll
        for (int o = 16; o > 0; o >>= 1) {
            s1 += __shfl_down_sync(0xffffffffu, s1, o);
            s2 += __shfl_down_sync(0xffffffffu, s2, o);
        }
        if ((tid & 31) == 0) { red[(tid >> 5) * 2] = s1; red[(tid >> 5) * 2 + 1] = s2; }
        __syncthreads();
        float t1 = red[0] + red[2] + red[4] + red[6];
        float t2 = red[1] + red[3] + red[5] + red[7];
        float mu = t1 / (float)OF;
        float var = t2 / (float)OF - mu * mu;
        float rs = rsqrtf(var + LN_EPS);
        float* op = out + ((size_t)b * NN + n) * OF;
        #pragma unroll
        for (int h = 0; h < NH; h++) {
            int j = h * DH + tid;
            op[j] = (acc[b][h] - mu) * rs * gamma[j] + beta[j];
        }
        __syncthreads();
    }
}

extern "C" void kernel_launch(void* const* d_in, const int* in_sizes, int n_in,
                              void* d_out, int out_size) {
    const float* x     = (const float*)d_in[0];
    const void*  ei    = d_in[1];
    const float* W     = (const float*)d_in[2];
    const float* a     = (const float*)d_in[3];
    const float* gamma = (const float*)d_in[4];
    const float* beta  = (const float*)d_in[5];
    float* out = (float*)d_out;

    static cudaStream_t s1 = nullptr;
    static cudaEvent_t ev0 = nullptr, ev1 = nullptr;
    if (!s1) {
        cudaStreamCreateWithFlags(&s1, cudaStreamNonBlocking);
        cudaEventCreateWithFlags(&ev0, cudaEventDisableTiming);
        cudaEventCreateWithFlags(&ev1, cudaEventDisableTiming);
        cudaFuncSetAttribute(k_gemm_mma, cudaFuncAttributeMaxDynamicSharedMemorySize, SMEMB);
    }

    k_detect<<<1, 32>>>((const int*)ei);

    // fork: CSR build on s1 (depends only on edges + is64)
    cudaEventRecord(ev0, 0);
    cudaStreamWaitEvent(s1, ev0, 0);
    k_init<<<(NN + 255) / 256, 256, 0, s1>>>();
    k_count<<<(NE + 255) / 256, 256, 0, s1>>>(ei);
    k_scan<<<1, 1024, 0, s1>>>();
    k_fill<<<(NE + 255) / 256, 256, 0, s1>>>(ei);
    cudaEventRecord(ev1, s1);

    // main: GEMM chain
    k_splitx<<<(NB * NN * KF / 4 + 255) / 256, 256>>>(x);
    k_convw<<<(NH * KF * DH + 255) / 256, 256>>>(W);
    {
        dim3 g(OF / 128, (NN + 127) / 128, NB);
        k_gemm_mma<<<g, 256, SMEMB>>>(a);
    }

    // join, then edge softmax + aggregate
    cudaStreamWaitEvent(0, ev1, 0);
    k_edge<<<(NE + 255) / 256, 256>>>(ei);
    k_exps<<<(NE + 255) / 256, 256>>>();
    k_agg<<<NN, 128>>>(ei, gamma, beta, out);
}

// round 7
// speedup vs baseline: 2.3766x; 1.0604x over previous
#include <cuda_runtime.h>
#include <cuda_bf16.h>
#include <cstdint>

#define NB 2
#define NN 30000
#define NE 120000
#define KF 512
#define NH 4
#define DH 128
#define OF 512
#define NBH 8
#define LN_EPS 1e-5f

__device__ float         g_t[(size_t)NN * NB * OF];   // [n][b][512]
__device__ __nv_bfloat16 g_wthi[OF * KF];  // [col][k], col = h*128+d
__device__ __nv_bfloat16 g_wtlo[OF * KF];
__device__ float         g_ssrc[(size_t)NN * NBH];    // [n][b*4+h]
__device__ float         g_sdst[(size_t)NN * NBH];
__device__ float         g_sc[(size_t)NE * NBH];      // [e][b*4+h]
__device__ float         g_sum[NBH];
__device__ int           g_cnt[NN];
__device__ int           g_off[NN + 1];
__device__ int           g_cur[NN];
__device__ int           g_eid[NE];
__device__ int           g_is64;

__device__ __forceinline__ int esrc(const void* ep, int e, int is64) {
    return is64 ? (int)((const long long*)ep)[e] : ((const int*)ep)[e];
}
__device__ __forceinline__ int edst(const void* ep, int e, int is64) {
    return is64 ? (int)((const long long*)ep)[NE + e] : ((const int*)ep)[NE + e];
}
__device__ __forceinline__ uint32_t smem_u32(const void* p) {
    uint32_t a;
    asm("{ .reg .u64 t; cvta.to.shared.u64 t, %1; cvt.u32.u64 %0, t; }" : "=r"(a) : "l"(p));
    return a;
}
__device__ __forceinline__ void cpa16(uint32_t dst, const void* src) {
    asm volatile("cp.async.ca.shared.global [%0], [%1], 16;"
                 :: "r"(dst), "l"(src) : "memory");
}

// ---------------- prep kernels ----------------
__global__ void k_detect(const int* ei32) {
    if (threadIdx.x == 0) {
        int ok = 1;
        for (int j = 0; j < 64; j++)
            if (ei32[2 * j + 1] != 0) ok = 0;
        g_is64 = ok;
    }
}
__global__ void k_init() {
    int i = blockIdx.x * blockDim.x + threadIdx.x;
    if (i < NN) g_cnt[i] = 0;
    if (i < NBH) g_sum[i] = 0.f;
}
__global__ void k_convw(const float* __restrict__ W) {
    int i = blockIdx.x * blockDim.x + threadIdx.x;  // h,k,d
    if (i >= NH * KF * DH) return;
    int h = i / (KF * DH), r = i % (KF * DH), k = r / DH, d = r % DH;
    float v = W[i];
    __nv_bfloat16 hi = __float2bfloat16(v);
    __nv_bfloat16 lo = __float2bfloat16(v - __bfloat162float(hi));
    int n = h * DH + d;
    g_wthi[(size_t)n * KF + k] = hi;
    g_wtlo[(size_t)n * KF + k] = lo;
}

// ---------------- mma.sync GEMM: 128x128 per CTA, K=512, 3-term bf16 -------
// SMEM layout per buffer: A_hi[0], A_lo[TERMB], B_hi[MATB], B_lo[MATB+TERMB]
#define PITCHB 80
#define TERMB  10240
#define MATB   20480
#define BUFB   40960
#define SMEMB  81920

__device__ __forceinline__ void ldgA(float4* ar, const float* __restrict__ xb,
                                     int m0, int kc, int tid) {
    #pragma unroll
    for (int j = 0; j < 4; j++) {
        int idx = j * 256 + tid;
        int row = idx >> 3, c4 = idx & 7;
        int gr = m0 + row;
        ar[j] = (gr < NN) ? *(const float4*)(xb + (size_t)gr * KF + kc * 32 + c4 * 4)
                          : make_float4(0.f, 0.f, 0.f, 0.f);
    }
}
__device__ __forceinline__ void stsA(const float4* ar, char* sm, int buf, int tid) {
    char* base = sm + buf * BUFB;
    #pragma unroll
    for (int j = 0; j < 4; j++) {
        int idx = j * 256 + tid;
        int row = idx >> 3, c4 = idx & 7;
        float4 v = ar[j];
        __nv_bfloat16 h0 = __float2bfloat16(v.x), h1 = __float2bfloat16(v.y);
        __nv_bfloat16 h2 = __float2bfloat16(v.z), h3 = __float2bfloat16(v.w);
        uint32_t hi0 = (uint32_t)__bfloat16_as_ushort(h0) |
                       ((uint32_t)__bfloat16_as_ushort(h1) << 16);
        uint32_t hi1 = (uint32_t)__bfloat16_as_ushort(h2) |
                       ((uint32_t)__bfloat16_as_ushort(h3) << 16);
        __nv_bfloat16 l0 = __float2bfloat16(v.x - __bfloat162float(h0));
        __nv_bfloat16 l1 = __float2bfloat16(v.y - __bfloat162float(h1));
        __nv_bfloat16 l2 = __float2bfloat16(v.z - __bfloat162float(h2));
        __nv_bfloat16 l3 = __float2bfloat16(v.w - __bfloat162float(h3));
        uint32_t lo0 = (uint32_t)__bfloat16_as_ushort(l0) |
                       ((uint32_t)__bfloat16_as_ushort(l1) << 16);
        uint32_t lo1 = (uint32_t)__bfloat16_as_ushort(l2) |
                       ((uint32_t)__bfloat16_as_ushort(l3) << 16);
        char* p = base + row * PITCHB + c4 * 8;
        *(uint2*)p = make_uint2(hi0, hi1);
        *(uint2*)(p + TERMB) = make_uint2(lo0, lo1);
    }
}
__device__ __forceinline__ void loadB(uint32_t sb, int buf, int kc, int bn, int tid) {
    #pragma unroll
    for (int i = 0; i < 4; i++) {
        int idx = i * 256 + tid;          // 0..1023
        int term = idx >> 9;
        int rr = idx & 511;
        int row = rr >> 2, seg = rr & 3;
        uint32_t dst = sb + buf * BUFB + MATB + term * TERMB + row * PITCHB + seg * 16;
        const __nv_bfloat16* src =
            (term ? g_wtlo : g_wthi) + (size_t)(bn + row) * KF + kc * 32 + seg * 8;
        cpa16(dst, src);
    }
    asm volatile("cp.async.commit_group;" ::: "memory");
}

#define MMA_BF16(c, a0, a1, a2, a3, b0, b1) \
    asm volatile( \
        "mma.sync.aligned.m16n8k16.row.col.f32.bf16.bf16.f32 " \
        "{%0,%1,%2,%3}, {%4,%5,%6,%7}, {%8,%9}, {%0,%1,%2,%3};" \
        : "+f"((c)[0]), "+f"((c)[1]), "+f"((c)[2]), "+f"((c)[3]) \
        : "r"(a0), "r"(a1), "r"(a2), "r"(a3), "r"(b0), "r"(b1))

__global__ __launch_bounds__(256, 2) void k_gemm_mma(const float* __restrict__ x,
                                                     const float* __restrict__ ga) {
    extern __shared__ float4 smf4[];
    char* sm = (char*)smf4;
    uint32_t sb = smem_u32(sm);
    int tid = threadIdx.x, lid = tid & 31, wid = tid >> 5;
    int gid = lid >> 2, tig = lid & 3;
    int wM = wid & 3, wN = wid >> 2;
    int hx = blockIdx.x;
    int m0 = blockIdx.y * 128, bn = hx * 128;
    int b = blockIdx.z;
    const float* xb = x + (size_t)b * NN * KF;

    float acc[2][8][4];
    #pragma unroll
    for (int mi = 0; mi < 2; mi++)
        #pragma unroll
        for (int ni = 0; ni < 8; ni++)
            #pragma unroll
            for (int q = 0; q < 4; q++) acc[mi][ni][q] = 0.f;

    float4 ar[4];
    ldgA(ar, xb, m0, 0, tid);
    stsA(ar, sm, 0, tid);
    loadB(sb, 0, 0, bn, tid);
    ldgA(ar, xb, m0, 1, tid);

    for (int kc = 0; kc < 16; kc++) {
        if (kc < 15) {
            stsA(ar, sm, (kc + 1) & 1, tid);
            loadB(sb, (kc + 1) & 1, kc + 1, bn, tid);
            if (kc < 14) ldgA(ar, xb, m0, kc + 2, tid);
            asm volatile("cp.async.wait_group 1;" ::: "memory");
        } else {
            asm volatile("cp.async.wait_group 0;" ::: "memory");
        }
        __syncthreads();
        const char* As = sm + (kc & 1) * BUFB;
        const char* Bs = As + MATB;
        #pragma unroll
        for (int s = 0; s < 2; s++) {
            int k0 = s * 16 + tig * 2;
            uint32_t ah[2][4];
            #pragma unroll
            for (int mi = 0; mi < 2; mi++) {
                const char* p = As + (wM * 32 + mi * 16 + gid) * PITCHB + k0 * 2;
                ah[mi][0] = *(const uint32_t*)p;
                ah[mi][1] = *(const uint32_t*)(p + 8 * PITCHB);
                ah[mi][2] = *(const uint32_t*)(p + 16);
                ah[mi][3] = *(const uint32_t*)(p + 8 * PITCHB + 16);
            }
            uint32_t bh_[8][2];
            #pragma unroll
            for (int ni = 0; ni < 8; ni++) {
                const char* p = Bs + (wN * 64 + ni * 8 + gid) * PITCHB + k0 * 2;
                bh_[ni][0] = *(const uint32_t*)p;
                bh_[ni][1] = *(const uint32_t*)(p + 16);
            }
            #pragma unroll
            for (int ni = 0; ni < 8; ni++) {
                MMA_BF16(acc[0][ni], ah[0][0], ah[0][1], ah[0][2], ah[0][3], bh_[ni][0], bh_[ni][1]);
                MMA_BF16(acc[1][ni], ah[1][0], ah[1][1], ah[1][2], ah[1][3], bh_[ni][0], bh_[ni][1]);
            }
            #pragma unroll
            for (int mi = 0; mi < 2; mi++) {
                const char* p = As + TERMB + (wM * 32 + mi * 16 + gid) * PITCHB + k0 * 2;
                uint32_t al0 = *(const uint32_t*)p;
                uint32_t al1 = *(const uint32_t*)(p + 8 * PITCHB);
                uint32_t al2 = *(const uint32_t*)(p + 16);
                uint32_t al3 = *(const uint32_t*)(p + 8 * PITCHB + 16);
                #pragma unroll
                for (int ni = 0; ni < 8; ni++)
                    MMA_BF16(acc[mi][ni], al0, al1, al2, al3, bh_[ni][0], bh_[ni][1]);
            }
            #pragma unroll
            for (int ni = 0; ni < 8; ni++) {
                const char* p = Bs + TERMB + (wN * 64 + ni * 8 + gid) * PITCHB + k0 * 2;
                uint32_t bl0 = *(const uint32_t*)p;
                uint32_t bl1 = *(const uint32_t*)(p + 16);
                MMA_BF16(acc[0][ni], ah[0][0], ah[0][1], ah[0][2], ah[0][3], bl0, bl1);
                MMA_BF16(acc[1][ni], ah[1][0], ah[1][1], ah[1][2], ah[1][3], bl0, bl1);
            }
        }
        __syncthreads();
    }

    // epilogue: write g_t[n][b][512] + fused s_src/s_dst dots for head hx
    float psrc[2][2] = {{0.f, 0.f}, {0.f, 0.f}};
    float pdst[2][2] = {{0.f, 0.f}, {0.f, 0.f}};
    #pragma unroll
    for (int mi = 0; mi < 2; mi++) {
        #pragma unroll
        for (int ni = 0; ni < 8; ni++) {
            int row = m0 + wM * 32 + mi * 16 + gid;
            int d0 = wN * 64 + ni * 8 + tig * 2;
            float c0 = acc[mi][ni][0], c1 = acc[mi][ni][1];
            float c2 = acc[mi][ni][2], c3 = acc[mi][ni][3];
            float a0 = __ldg(ga + hx * 256 + d0);
            float a1 = __ldg(ga + hx * 256 + d0 + 1);
            float e0 = __ldg(ga + hx * 256 + 128 + d0);
            float e1 = __ldg(ga + hx * 256 + 128 + d0 + 1);
            psrc[mi][0] += c0 * a0 + c1 * a1;
            psrc[mi][1] += c2 * a0 + c3 * a1;
            pdst[mi][0] += c0 * e0 + c1 * e1;
            pdst[mi][1] += c2 * e0 + c3 * e1;
            float* base = g_t + ((size_t)row * NB + b) * OF + hx * 128 + d0;
            if (row < NN) *(float2*)base = make_float2(c0, c1);
            if (row + 8 < NN) *(float2*)(base + 8 * (size_t)(NB * OF)) = make_float2(c2, c3);
        }
    }
    #pragma unroll
    for (int mi = 0; mi < 2; mi++)
        #pragma unroll
        for (int hf = 0; hf < 2; hf++) {
            float v = psrc[mi][hf];
            v += __shfl_xor_sync(0xffffffffu, v, 1);
            v += __shfl_xor_sync(0xffffffffu, v, 2);
            psrc[mi][hf] = v;
            float w = pdst[mi][hf];
            w += __shfl_xor_sync(0xffffffffu, w, 1);
            w += __shfl_xor_sync(0xffffffffu, w, 2);
            pdst[mi][hf] = w;
        }
    float* sred = (float*)sm;  // [wN=2][128 rows][2]
    if (tig == 0) {
        #pragma unroll
        for (int mi = 0; mi < 2; mi++) {
            int r0 = wM * 32 + mi * 16 + gid;
            sred[(wN * 128 + r0) * 2]         = psrc[mi][0];
            sred[(wN * 128 + r0) * 2 + 1]     = pdst[mi][0];
            sred[(wN * 128 + r0 + 8) * 2]     = psrc[mi][1];
            sred[(wN * 128 + r0 + 8) * 2 + 1] = pdst[mi][1];
        }
    }
    __syncthreads();
    if (tid < 128) {
        int n = m0 + tid;
        if (n < NN) {
            float ss = sred[tid * 2] + sred[(128 + tid) * 2];
            float sd = sred[tid * 2 + 1] + sred[(128 + tid) * 2 + 1];
            g_ssrc[(size_t)n * NBH + b * 4 + hx] = ss;
            g_sdst[(size_t)n * NBH + b * 4 + hx] = sd;
        }
    }
}

// ---------------- fused edge softmax (no max pass) ----------------
__global__ __launch_bounds__(256) void k_sm(const void* ep) {
    __shared__ float wred[8][8];
    int tid = threadIdx.x, wid = tid >> 5, lid = tid & 31;
    int is64 = g_is64;
    int e = blockIdx.x * 256 + tid;
    float pv[8];
    if (e < NE) {
        int sn = esrc(ep, e, is64), dn = edst(ep, e, is64);
        const float* ps = g_ssrc + (size_t)sn * NBH;
        const float* pd = g_sdst + (size_t)dn * NBH;
        #pragma unroll
        for (int i = 0; i < 8; i++) {
            float s = ps[i] + pd[i];
            s = (s > 0.f) ? s : 0.2f * s;
            float p = __expf(s);
            pv[i] = p;
            g_sc[(size_t)e * NBH + i] = p;
        }
    } else {
        #pragma unroll
        for (int i = 0; i < 8; i++) pv[i] = 0.f;
    }
    #pragma unroll
    for (int i = 0; i < 8; i++) {
        float s = pv[i];
        #pragma unroll
        for (int o = 16; o > 0; o >>= 1) s += __shfl_xor_sync(0xffffffffu, s, o);
        if (lid == 0) wred[wid][i] = s;
    }
    __syncthreads();
    if (tid < 8) {
        float s = 0.f;
        #pragma unroll
        for (int w = 0; w < 8; w++) s += wred[w][tid];
        atomicAdd(&g_sum[tid], s);
    }
}

// ---------------- CSR build ----------------
__global__ void k_count(const void* ep) {
    int e = blockIdx.x * 256 + threadIdx.x;
    if (e < NE) atomicAdd(&g_cnt[edst(ep, e, g_is64)], 1);
}
__global__ __launch_bounds__(1024) void k_scan() {
    __shared__ int s[1024];
    int tid = threadIdx.x;
    const int C = (NN + 1023) / 1024;
    int base = tid * C;
    int sum = 0;
    for (int i = 0; i < C; i++) { int idx = base + i; if (idx < NN) sum += g_cnt[idx]; }
    s[tid] = sum;
    __syncthreads();
    for (int o = 1; o < 1024; o <<= 1) {
        int v = (tid >= o) ? s[tid - o] : 0;
        __syncthreads();
        s[tid] += v;
        __syncthreads();
    }
    int run = s[tid] - sum;
    for (int i = 0; i < C; i++) {
        int idx = base + i;
        if (idx < NN) { g_off[idx] = run; g_cur[idx] = run; run += g_cnt[idx]; }
    }
    if (tid == 1023) g_off[NN] = run;
}
__global__ void k_fill(const void* ep) {
    int e = blockIdx.x * 256 + threadIdx.x;
    if (e < NE) {
        int pos = atomicAdd(&g_cur[edst(ep, e, g_is64)], 1);
        g_eid[pos] = e;
    }
}

// ---------------- aggregate + layernorm ----------------
__global__ __launch_bounds__(128) void k_agg(const void* ep,
                                             const float* __restrict__ gamma,
                                             const float* __restrict__ beta,
                                             float* __restrict__ out) {
    __shared__ float red[8];
    int is64 = g_is64;
    int n = blockIdx.x;
    int tid = threadIdx.x;
    float acc[NB][NH] = {};
    int e0 = g_off[n], e1 = g_off[n + 1];
    for (int idx = e0; idx < e1; idx++) {
        int e = g_eid[idx];
        int sn = esrc(ep, e, is64);
        const float* trow = g_t + (size_t)sn * (NB * OF);
        float4 w0 = *(const float4*)(g_sc + (size_t)e * NBH);
        float4 w1 = *(const float4*)(g_sc + (size_t)e * NBH + 4);
        acc[0][0] += w0.x * trow[tid];
        acc[0][1] += w0.y * trow[128 + tid];
        acc[0][2] += w0.z * trow[256 + tid];
        acc[0][3] += w0.w * trow[384 + tid];
        acc[1][0] += w1.x * trow[512 + tid];
        acc[1][1] += w1.y * trow[640 + tid];
        acc[1][2] += w1.z * trow[768 + tid];
        acc[1][3] += w1.w * trow[896 + tid];
    }
    #pragma unroll
    for (int b = 0; b < NB; b++) {
        #pragma unroll
        for (int h = 0; h < NH; h++) acc[b][h] *= (1.f / g_sum[b * 4 + h]);
        float s1 = acc[b][0] + acc[b][1] + acc[b][2] + acc[b][3];
        float s2 = acc[b][0] * acc[b][0] + acc[b][1] * acc[b][1] +
                   acc[b][2] * acc[b][2] + acc[b][3] * acc[b][3];
        #pragma unroll
        for (int o = 16; o > 0; o >>= 1) {
            s1 += __shfl_down_sync(0xffffffffu, s1, o);
            s2 += __shfl_down_sync(0xffffffffu, s2, o);
        }
        if ((tid & 31) == 0) { red[(tid >> 5) * 2] = s1; red[(tid >> 5) * 2 + 1] = s2; }
        __syncthreads();
        float t1 = red[0] + red[2] + red[4] + red[6];
        float t2 = red[1] + red[3] + red[5] + red[7];
        float mu = t1 / (float)OF;
        float var = t2 / (float)OF - mu * mu;
        float rs = rsqrtf(var + LN_EPS);
        float* op = out + ((size_t)b * NN + n) * OF;
        #pragma unroll
        for (int h = 0; h < NH; h++) {
            int j = h * DH + tid;
            op[j] = (acc[b][h] - mu) * rs * gamma[j] + beta[j];
        }
        __syncthreads();
    }
}

extern "C" void kernel_launch(void* const* d_in, const int* in_sizes, int n_in,
                              void* d_out, int out_size) {
    const float* x     = (const float*)d_in[0];
    const void*  ei    = d_in[1];
    const float* W     = (const float*)d_in[2];
    const float* a     = (const float*)d_in[3];
    const float* gamma = (const float*)d_in[4];
    const float* beta  = (const float*)d_in[5];
    float* out = (float*)d_out;

    static cudaStream_t s1 = nullptr;
    static cudaEvent_t ev0 = nullptr, ev1 = nullptr;
    if (!s1) {
        cudaStreamCreateWithFlags(&s1, cudaStreamNonBlocking);
        cudaEventCreateWithFlags(&ev0, cudaEventDisableTiming);
        cudaEventCreateWithFlags(&ev1, cudaEventDisableTiming);
        cudaFuncSetAttribute(k_gemm_mma, cudaFuncAttributeMaxDynamicSharedMemorySize, SMEMB);
    }

    k_detect<<<1, 32>>>((const int*)ei);                       // 0
    k_convw<<<(NH * KF * DH + 255) / 256, 256>>>(W);           // 1

    cudaEventRecord(ev0, 0);
    cudaStreamWaitEvent(s1, ev0, 0);
    k_init<<<(NN + 255) / 256, 256, 0, s1>>>();                // 2
    k_count<<<(NE + 255) / 256, 256, 0, s1>>>(ei);             // 3
    k_scan<<<1, 1024, 0, s1>>>();                              // 4

    {
        dim3 g(OF / 128, (NN + 127) / 128, NB);
        k_gemm_mma<<<g, 256, SMEMB>>>(x, a);                   // 5 (ncu -s 5)
    }

    k_fill<<<(NE + 255) / 256, 256, 0, s1>>>(ei);              // 6
    cudaEventRecord(ev1, s1);

    cudaStreamWaitEvent(0, ev1, 0);
    k_sm<<<(NE + 255) / 256, 256>>>(ei);                       // 7
    k_agg<<<NN, 128>>>(ei, gamma, beta, out);                  // 8
}

// round 8
// speedup vs baseline: 2.4370x; 1.0254x over previous
#include <cuda_runtime.h>
#include <cuda_bf16.h>
#include <cstdint>

#define NB 2
#define NN 30000
#define NE 120000
#define KF 512
#define NH 4
#define DH 128
#define OF 512
#define NBH 8
#define LN_EPS 1e-5f

__device__ float         g_t[(size_t)NN * NB * OF];   // [n][b][512]
__device__ __nv_bfloat16 g_wthi[OF * KF];  // [col][k], col = h*128+d
__device__ __nv_bfloat16 g_wtlo[OF * KF];
__device__ float         g_ssrc[(size_t)NN * NBH];    // [n][b*4+h]
__device__ float         g_sdst[(size_t)NN * NBH];
__device__ float         g_sc[(size_t)NE * NBH];      // [e][b*4+h]
__device__ float         g_sum[NBH];
__device__ int           g_cnt[NN];
__device__ int           g_off[NN + 1];
__device__ int           g_cur[NN];
__device__ int           g_eid[NE];
__device__ int           g_is64;

__device__ __forceinline__ int esrc(const void* ep, int e, int is64) {
    return is64 ? (int)((const long long*)ep)[e] : ((const int*)ep)[e];
}
__device__ __forceinline__ int edst(const void* ep, int e, int is64) {
    return is64 ? (int)((const long long*)ep)[NE + e] : ((const int*)ep)[NE + e];
}
__device__ __forceinline__ uint32_t smem_u32(const void* p) {
    uint32_t a;
    asm("{ .reg .u64 t; cvta.to.shared.u64 t, %1; cvt.u32.u64 %0, t; }" : "=r"(a) : "l"(p));
    return a;
}
__device__ __forceinline__ void cpa16(uint32_t dst, const void* src) {
    asm volatile("cp.async.ca.shared.global [%0], [%1], 16;"
                 :: "r"(dst), "l"(src) : "memory");
}
__device__ __forceinline__ void ldsm_x4(uint32_t addr, uint32_t& r0, uint32_t& r1,
                                        uint32_t& r2, uint32_t& r3) {
    asm volatile("ldmatrix.sync.aligned.m8n8.x4.shared.b16 {%0,%1,%2,%3}, [%4];"
                 : "=r"(r0), "=r"(r1), "=r"(r2), "=r"(r3) : "r"(addr));
}

// ---------------- prep kernels ----------------
__global__ void k_detect(const int* ei32) {
    if (threadIdx.x == 0) {
        int ok = 1;
        for (int j = 0; j < 64; j++)
            if (ei32[2 * j + 1] != 0) ok = 0;
        g_is64 = ok;
    }
}
__global__ void k_init() {
    int i = blockIdx.x * blockDim.x + threadIdx.x;
    if (i < NN) g_cnt[i] = 0;
    if (i < NBH) g_sum[i] = 0.f;
}
__global__ void k_convw(const float* __restrict__ W) {
    int i = blockIdx.x * blockDim.x + threadIdx.x;  // h,k,d
    if (i >= NH * KF * DH) return;
    int h = i / (KF * DH), r = i % (KF * DH), k = r / DH, d = r % DH;
    float v = W[i];
    __nv_bfloat16 hi = __float2bfloat16(v);
    __nv_bfloat16 lo = __float2bfloat16(v - __bfloat162float(hi));
    int n = h * DH + d;
    g_wthi[(size_t)n * KF + k] = hi;
    g_wtlo[(size_t)n * KF + k] = lo;
}

// ---------------- mma.sync GEMM: 128x128 per CTA, K=512, 3-term bf16 -------
#define PITCHB 80
#define TERMB  10240
#define MATB   20480
#define BUFB   40960
#define SMEMB  81920

__device__ __forceinline__ void ldgA(float4* ar, const float* __restrict__ xb,
                                     int m0, int kc, int tid) {
    #pragma unroll
    for (int j = 0; j < 4; j++) {
        int idx = j * 256 + tid;
        int row = idx >> 3, c4 = idx & 7;
        int gr = m0 + row;
        ar[j] = (gr < NN) ? *(const float4*)(xb + (size_t)gr * KF + kc * 32 + c4 * 4)
                          : make_float4(0.f, 0.f, 0.f, 0.f);
    }
}
__device__ __forceinline__ void stsA(const float4* ar, char* sm, int buf, int tid) {
    char* base = sm + buf * BUFB;
    #pragma unroll
    for (int j = 0; j < 4; j++) {
        int idx = j * 256 + tid;
        int row = idx >> 3, c4 = idx & 7;
        float4 v = ar[j];
        __nv_bfloat16 h0 = __float2bfloat16(v.x), h1 = __float2bfloat16(v.y);
        __nv_bfloat16 h2 = __float2bfloat16(v.z), h3 = __float2bfloat16(v.w);
        uint32_t hi0 = (uint32_t)__bfloat16_as_ushort(h0) |
                       ((uint32_t)__bfloat16_as_ushort(h1) << 16);
        uint32_t hi1 = (uint32_t)__bfloat16_as_ushort(h2) |
                       ((uint32_t)__bfloat16_as_ushort(h3) << 16);
        __nv_bfloat16 l0 = __float2bfloat16(v.x - __bfloat162float(h0));
        __nv_bfloat16 l1 = __float2bfloat16(v.y - __bfloat162float(h1));
        __nv_bfloat16 l2 = __float2bfloat16(v.z - __bfloat162float(h2));
        __nv_bfloat16 l3 = __float2bfloat16(v.w - __bfloat162float(h3));
        uint32_t lo0 = (uint32_t)__bfloat16_as_ushort(l0) |
                       ((uint32_t)__bfloat16_as_ushort(l1) << 16);
        uint32_t lo1 = (uint32_t)__bfloat16_as_ushort(l2) |
                       ((uint32_t)__bfloat16_as_ushort(l3) << 16);
        char* p = base + row * PITCHB + c4 * 8;
        *(uint2*)p = make_uint2(hi0, hi1);
        *(uint2*)(p + TERMB) = make_uint2(lo0, lo1);
    }
}
__device__ __forceinline__ void loadB(uint32_t sb, int buf, int kc, int bn, int tid) {
    #pragma unroll
    for (int i = 0; i < 4; i++) {
        int idx = i * 256 + tid;
        int term = idx >> 9;
        int rr = idx & 511;
        int row = rr >> 2, seg = rr & 3;
        uint32_t dst = sb + buf * BUFB + MATB + term * TERMB + row * PITCHB + seg * 16;
        const __nv_bfloat16* src =
            (term ? g_wtlo : g_wthi) + (size_t)(bn + row) * KF + kc * 32 + seg * 8;
        cpa16(dst, src);
    }
    asm volatile("cp.async.commit_group;" ::: "memory");
}

#define MMA_BF16(c, a0, a1, a2, a3, b0, b1) \
    asm volatile( \
        "mma.sync.aligned.m16n8k16.row.col.f32.bf16.bf16.f32 " \
        "{%0,%1,%2,%3}, {%4,%5,%6,%7}, {%8,%9}, {%0,%1,%2,%3};" \
        : "+f"((c)[0]), "+f"((c)[1]), "+f"((c)[2]), "+f"((c)[3]) \
        : "r"(a0), "r"(a1), "r"(a2), "r"(a3), "r"(b0), "r"(b1))

__global__ __launch_bounds__(256, 2) void k_gemm_mma(const float* __restrict__ x,
                                                     const float* __restrict__ ga) {
    extern __shared__ float4 smf4[];
    char* sm = (char*)smf4;
    uint32_t sb = smem_u32(sm);
    int tid = threadIdx.x, lid = tid & 31, wid = tid >> 5;
    int gid = lid >> 2, tig = lid & 3;
    int wM = wid & 3, wN = wid >> 2;
    int hx = blockIdx.x;
    int m0 = blockIdx.y * 128, bn = hx * 128;
    int b = blockIdx.z;
    const float* xb = x + (size_t)b * NN * KF;

    // ldmatrix lane-derived byte offsets
    uint32_t aoff = (uint32_t)((lid & 15) * PITCHB + (((lid >> 4) << 3)) * 2);
    uint32_t boff = (uint32_t)((((lid & 7) + ((lid >> 4) << 3))) * PITCHB +
                               ((((lid >> 3) & 1) << 3)) * 2);

    float acc[2][8][4];
    #pragma unroll
    for (int mi = 0; mi < 2; mi++)
        #pragma unroll
        for (int ni = 0; ni < 8; ni++)
            #pragma unroll
            for (int q = 0; q < 4; q++) acc[mi][ni][q] = 0.f;

    float4 ar[4];
    ldgA(ar, xb, m0, 0, tid);
    stsA(ar, sm, 0, tid);
    loadB(sb, 0, 0, bn, tid);
    ldgA(ar, xb, m0, 1, tid);

    for (int kc = 0; kc < 16; kc++) {
        if (kc < 15) {
            stsA(ar, sm, (kc + 1) & 1, tid);
            loadB(sb, (kc + 1) & 1, kc + 1, bn, tid);
            if (kc < 14) ldgA(ar, xb, m0, kc + 2, tid);
            asm volatile("cp.async.wait_group 1;" ::: "memory");
        } else {
            asm volatile("cp.async.wait_group 0;" ::: "memory");
        }
        __syncthreads();
        uint32_t sA = sb + (kc & 1) * BUFB;
        uint32_t sB = sA + MATB;
        #pragma unroll
        for (int s = 0; s < 2; s++) {
            uint32_t Abase = sA + wM * 32 * PITCHB + aoff + s * 32;
            uint32_t Bbase = sB + wN * 64 * PITCHB + boff + s * 32;
            uint32_t ah[2][4];
            ldsm_x4(Abase,                ah[0][0], ah[0][1], ah[0][2], ah[0][3]);
            ldsm_x4(Abase + 16 * PITCHB,  ah[1][0], ah[1][1], ah[1][2], ah[1][3]);
            uint32_t bh_[8][2];
            #pragma unroll
            for (int j = 0; j < 4; j++)
                ldsm_x4(Bbase + j * 16 * PITCHB,
                        bh_[2 * j][0], bh_[2 * j][1], bh_[2 * j + 1][0], bh_[2 * j + 1][1]);
            #pragma unroll
            for (int ni = 0; ni < 8; ni++) {
                MMA_BF16(acc[0][ni], ah[0][0], ah[0][1], ah[0][2], ah[0][3], bh_[ni][0], bh_[ni][1]);
                MMA_BF16(acc[1][ni], ah[1][0], ah[1][1], ah[1][2], ah[1][3], bh_[ni][0], bh_[ni][1]);
            }
            // A_lo x B_hi
            uint32_t al[2][4];
            ldsm_x4(Abase + TERMB,               al[0][0], al[0][1], al[0][2], al[0][3]);
            ldsm_x4(Abase + TERMB + 16 * PITCHB, al[1][0], al[1][1], al[1][2], al[1][3]);
            #pragma unroll
            for (int ni = 0; ni < 8; ni++) {
                MMA_BF16(acc[0][ni], al[0][0], al[0][1], al[0][2], al[0][3], bh_[ni][0], bh_[ni][1]);
                MMA_BF16(acc[1][ni], al[1][0], al[1][1], al[1][2], al[1][3], bh_[ni][0], bh_[ni][1]);
            }
            // A_hi x B_lo
            uint32_t bl[8][2];
            #pragma unroll
            for (int j = 0; j < 4; j++)
                ldsm_x4(Bbase + TERMB + j * 16 * PITCHB,
                        bl[2 * j][0], bl[2 * j][1], bl[2 * j + 1][0], bl[2 * j + 1][1]);
            #pragma unroll
            for (int ni = 0; ni < 8; ni++) {
                MMA_BF16(acc[0][ni], ah[0][0], ah[0][1], ah[0][2], ah[0][3], bl[ni][0], bl[ni][1]);
                MMA_BF16(acc[1][ni], ah[1][0], ah[1][1], ah[1][2], ah[1][3], bl[ni][0], bl[ni][1]);
            }
        }
        __syncthreads();
    }

    // epilogue: write g_t[n][b][512] + fused s_src/s_dst dots for head hx
    float psrc[2][2] = {{0.f, 0.f}, {0.f, 0.f}};
    float pdst[2][2] = {{0.f, 0.f}, {0.f, 0.f}};
    #pragma unroll
    for (int mi = 0; mi < 2; mi++) {
        #pragma unroll
        for (int ni = 0; ni < 8; ni++) {
            int row = m0 + wM * 32 + mi * 16 + gid;
            int d0 = wN * 64 + ni * 8 + tig * 2;
            float c0 = acc[mi][ni][0], c1 = acc[mi][ni][1];
            float c2 = acc[mi][ni][2], c3 = acc[mi][ni][3];
            float a0 = __ldg(ga + hx * 256 + d0);
            float a1 = __ldg(ga + hx * 256 + d0 + 1);
            float e0 = __ldg(ga + hx * 256 + 128 + d0);
            float e1 = __ldg(ga + hx * 256 + 128 + d0 + 1);
            psrc[mi][0] += c0 * a0 + c1 * a1;
            psrc[mi][1] += c2 * a0 + c3 * a1;
            pdst[mi][0] += c0 * e0 + c1 * e1;
            pdst[mi][1] += c2 * e0 + c3 * e1;
            float* base = g_t + ((size_t)row * NB + b) * OF + hx * 128 + d0;
            if (row < NN) *(float2*)base = make_float2(c0, c1);
            if (row + 8 < NN) *(float2*)(base + 8 * (size_t)(NB * OF)) = make_float2(c2, c3);
        }
    }
    #pragma unroll
    for (int mi = 0; mi < 2; mi++)
        #pragma unroll
        for (int hf = 0; hf < 2; hf++) {
            float v = psrc[mi][hf];
            v += __shfl_xor_sync(0xffffffffu, v, 1);
            v += __shfl_xor_sync(0xffffffffu, v, 2);
            psrc[mi][hf] = v;
            float w = pdst[mi][hf];
            w += __shfl_xor_sync(0xffffffffu, w, 1);
            w += __shfl_xor_sync(0xffffffffu, w, 2);
            pdst[mi][hf] = w;
        }
    float* sred = (float*)sm;
    if (tig == 0) {
        #pragma unroll
        for (int mi = 0; mi < 2; mi++) {
            int r0 = wM * 32 + mi * 16 + gid;
            sred[(wN * 128 + r0) * 2]         = psrc[mi][0];
            sred[(wN * 128 + r0) * 2 + 1]     = pdst[mi][0];
            sred[(wN * 128 + r0 + 8) * 2]     = psrc[mi][1];
            sred[(wN * 128 + r0 + 8) * 2 + 1] = pdst[mi][1];
        }
    }
    __syncthreads();
    if (tid < 128) {
        int n = m0 + tid;
        if (n < NN) {
            float ss = sred[tid * 2] + sred[(128 + tid) * 2];
            float sd = sred[tid * 2 + 1] + sred[(128 + tid) * 2 + 1];
            g_ssrc[(size_t)n * NBH + b * 4 + hx] = ss;
            g_sdst[(size_t)n * NBH + b * 4 + hx] = sd;
        }
    }
}

// ---------------- fused edge softmax (no max pass) ----------------
__global__ __launch_bounds__(256) void k_sm(const void* ep) {
    __shared__ float wred[8][8];
    int tid = threadIdx.x, wid = tid >> 5, lid = tid & 31;
    int is64 = g_is64;
    int e = blockIdx.x * 256 + tid;
    float pv[8];
    if (e < NE) {
        int sn = esrc(ep, e, is64), dn = edst(ep, e, is64);
        const float* ps = g_ssrc + (size_t)sn * NBH;
        const float* pd = g_sdst + (size_t)dn * NBH;
        #pragma unroll
        for (int i = 0; i < 8; i++) {
            float s = ps[i] + pd[i];
            s = (s > 0.f) ? s : 0.2f * s;
            float p = __expf(s);
            pv[i] = p;
            g_sc[(size_t)e * NBH + i] = p;
        }
    } else {
        #pragma unroll
        for (int i = 0; i < 8; i++) pv[i] = 0.f;
    }
    #pragma unroll
    for (int i = 0; i < 8; i++) {
        float s = pv[i];
        #pragma unroll
        for (int o = 16; o > 0; o >>= 1) s += __shfl_xor_sync(0xffffffffu, s, o);
        if (lid == 0) wred[wid][i] = s;
    }
    __syncthreads();
    if (tid < 8) {
        float s = 0.f;
        #pragma unroll
        for (int w = 0; w < 8; w++) s += wred[w][tid];
        atomicAdd(&g_sum[tid], s);
    }
}

// ---------------- CSR build ----------------
__global__ void k_count(const void* ep) {
    int e = blockIdx.x * 256 + threadIdx.x;
    if (e < NE) atomicAdd(&g_cnt[edst(ep, e, g_is64)], 1);
}
__global__ __launch_bounds__(1024) void k_scan() {
    __shared__ int s[1024];
    int tid = threadIdx.x;
    const int C = (NN + 1023) / 1024;
    int base = tid * C;
    int sum = 0;
    for (int i = 0; i < C; i++) { int idx = base + i; if (idx < NN) sum += g_cnt[idx]; }
    s[tid] = sum;
    __syncthreads();
    for (int o = 1; o < 1024; o <<= 1) {
        int v = (tid >= o) ? s[tid - o] : 0;
        __syncthreads();
        s[tid] += v;
        __syncthreads();
    }
    int run = s[tid] - sum;
    for (int i = 0; i < C; i++) {
        int idx = base + i;
        if (idx < NN) { g_off[idx] = run; g_cur[idx] = run; run += g_cnt[idx]; }
    }
    if (tid == 1023) g_off[NN] = run;
}
__global__ void k_fill(const void* ep) {
    int e = blockIdx.x * 256 + threadIdx.x;
    if (e < NE) {
        int pos = atomicAdd(&g_cur[edst(ep, e, g_is64)], 1);
        g_eid[pos] = e;
    }
}

// ---------------- aggregate + layernorm ----------------
__global__ __launch_bounds__(128) void k_agg(const void* ep,
                                             const float* __restrict__ gamma,
                                             const float* __restrict__ beta,
                                             float* __restrict__ out) {
    __shared__ float red[8];
    int is64 = g_is64;
    int n = blockIdx.x;
    int tid = threadIdx.x;
    float acc[NB][NH] = {};
    int e0 = g_off[n], e1 = g_off[n + 1];
    for (int idx = e0; idx < e1; idx++) {
        int e = g_eid[idx];
        int sn = esrc(ep, e, is64);
        const float* trow = g_t + (size_t)sn * (NB * OF);
        float4 w0 = *(const float4*)(g_sc + (size_t)e * NBH);
        float4 w1 = *(const float4*)(g_sc + (size_t)e * NBH + 4);
        acc[0][0] += w0.x * trow[tid];
        acc[0][1] += w0.y * trow[128 + tid];
        acc[0][2] += w0.z * trow[256 + tid];
        acc[0][3] += w0.w * trow[384 + tid];
        acc[1][0] += w1.x * trow[512 + tid];
        acc[1][1] += w1.y * trow[640 + tid];
        acc[1][2] += w1.z * trow[768 + tid];
        acc[1][3] += w1.w * trow[896 + tid];
    }
    #pragma unroll
    for (int b = 0; b < NB; b++) {
        #pragma unroll
        for (int h = 0; h < NH; h++) acc[b][h] *= (1.f / g_sum[b * 4 + h]);
        float s1 = acc[b][0] + acc[b][1] + acc[b][2] + acc[b][3];
        float s2 = acc[b][0] * acc[b][0] + acc[b][1] * acc[b][1] +
                   acc[b][2] * acc[b][2] + acc[b][3] * acc[b][3];
        #pragma unroll
        for (int o = 16; o > 0; o >>= 1) {
            s1 += __shfl_down_sync(0xffffffffu, s1, o);
            s2 += __shfl_down_sync(0xffffffffu, s2, o);
        }
        if ((tid & 31) == 0) { red[(tid >> 5) * 2] = s1; red[(tid >> 5) * 2 + 1] = s2; }
        __syncthreads();
        float t1 = red[0] + red[2] + red[4] + red[6];
        float t2 = red[1] + red[3] + red[5] + red[7];
        float mu = t1 / (float)OF;
        float var = t2 / (float)OF - mu * mu;
        float rs = rsqrtf(var + LN_EPS);
        float* op = out + ((size_t)b * NN + n) * OF;
        #pragma unroll
        for (int h = 0; h < NH; h++) {
            int j = h * DH + tid;
            op[j] = (acc[b][h] - mu) * rs * gamma[j] + beta[j];
        }
        __syncthreads();
    }
}

extern "C" void kernel_launch(void* const* d_in, const int* in_sizes, int n_in,
                              void* d_out, int out_size) {
    const float* x     = (const float*)d_in[0];
    const void*  ei    = d_in[1];
    const float* W     = (const float*)d_in[2];
    const float* a     = (const float*)d_in[3];
    const float* gamma = (const float*)d_in[4];
    const float* beta  = (const float*)d_in[5];
    float* out = (float*)d_out;

    static cudaStream_t s1 = nullptr;
    static cudaEvent_t ev0 = nullptr, ev1 = nullptr;
    if (!s1) {
        cudaStreamCreateWithFlags(&s1, cudaStreamNonBlocking);
        cudaEventCreateWithFlags(&ev0, cudaEventDisableTiming);
        cudaEventCreateWithFlags(&ev1, cudaEventDisableTiming);
        cudaFuncSetAttribute(k_gemm_mma, cudaFuncAttributeMaxDynamicSharedMemorySize, SMEMB);
    }

    k_convw<<<(NH * KF * DH + 255) / 256, 256>>>(W);           // launch 0

    cudaEventRecord(ev0, 0);
    cudaStreamWaitEvent(s1, ev0, 0);
    k_detect<<<1, 32, 0, s1>>>((const int*)ei);                // 1
    k_init<<<(NN + 255) / 256, 256, 0, s1>>>();                // 2
    k_count<<<(NE + 255) / 256, 256, 0, s1>>>(ei);             // 3
    k_scan<<<1, 1024, 0, s1>>>();                              // 4

    {
        dim3 g(OF / 128, (NN + 127) / 128, NB);
        k_gemm_mma<<<g, 256, SMEMB>>>(x, a);                   // 5 (ncu -s 5)
    }

    k_fill<<<(NE + 255) / 256, 256, 0, s1>>>(ei);              // 6
    cudaEventRecord(ev1, s1);

    cudaStreamWaitEvent(0, ev1, 0);
    k_sm<<<(NE + 255) / 256, 256>>>(ei);                       // 7
    k_agg<<<NN, 128>>>(ei, gamma, beta, out);                  // 8
}